// round 11
// baseline (speedup 1.0000x reference)
#include <cuda_runtime.h>
#include <cuda_bf16.h>
#include <math.h>

#define T_SEQ   512
#define GATES   500
#define HID     125
#define DHID    250      // 2*HID
#define MLPH    512
#define NN      512

// Scratch (device globals; no allocation allowed)
__device__ float g_A[2 * T_SEQ * GATES];   // input projections (fwd/bwd)
__device__ float g_H[T_SEQ * DHID];        // concat hidden states
__device__ float g_P[2 * NN * MLPH];       // Pa, Pb(+b1)

// ---------------------------------------------------------------------------
// helpers
// ---------------------------------------------------------------------------
typedef unsigned long long ull;

__device__ __forceinline__ ull ffma2u(ull a, ull b, ull c) {
    ull d;
    asm("fma.rn.f32x2 %0, %1, %2, %3;" : "=l"(d) : "l"(a), "l"(b), "l"(c));
    return d;
}
__device__ __forceinline__ ull fadd2u(ull a, ull b) {
    ull d;
    asm("add.rn.f32x2 %0, %1, %2;" : "=l"(d) : "l"(a), "l"(b));
    return d;
}
__device__ __forceinline__ float2 u2f2(ull v) {
    float2 r;
    asm("mov.b64 {%0, %1}, %2;" : "=f"(r.x), "=f"(r.y) : "l"(v));
    return r;
}
// unpack packed bf16x2 (lo16 = even col, hi16 = odd col) to packed f32x2
__device__ __forceinline__ ull unpk(unsigned int v) {
    ull d;
    asm("{\n\t"
        ".reg .b32 lo, hi;\n\t"
        "shl.b32 lo, %1, 16;\n\t"
        "and.b32 hi, %1, 0xFFFF0000;\n\t"
        "mov.b64 %0, {lo, hi};\n\t"
        "}" : "=l"(d) : "r"(v));
    return d;
}
__device__ __forceinline__ float tanh_mufu(float x) {
    float y;
    asm("tanh.approx.f32 %0, %1;" : "=f"(y) : "f"(x));
    return y;
}
__device__ __forceinline__ float sig_mufu(float x) {
    return 0.5f * tanh_mufu(0.5f * x) + 0.5f;
}

// no-op kernels to keep the ncu capture slot on lstm_kernel
__device__ int g_sink;
__global__ void nudge_kernel() {
    if (threadIdx.x > 4096) g_sink = 1;   // never taken
}

// ---------------------------------------------------------------------------
// Input projection, both directions in one launch.
// ---------------------------------------------------------------------------
__global__ void __launch_bounds__(256) proj_kernel(
    const float* __restrict__ x,
    const float* __restrict__ Wih_f, const float* __restrict__ bih_f,
    const float* __restrict__ bhh_f,
    const float* __restrict__ Wih_b, const float* __restrict__ bih_b,
    const float* __restrict__ bhh_b,
    float* __restrict__ Aout)
{
    const int dir = blockIdx.z;
    const float* __restrict__ W  = dir ? Wih_b : Wih_f;
    const float* __restrict__ bi = dir ? bih_b : bih_f;
    const float* __restrict__ bh = dir ? bhh_b : bhh_f;
    float* __restrict__ C = Aout + dir * (T_SEQ * GATES);

    __shared__ float As[16][34];
    __shared__ float Bs[16][34];

    const int tid = threadIdx.x;
    const int ti = tid & 15;
    const int tn = tid >> 4;
    const int m0 = blockIdx.x * 32;
    const int n0 = blockIdx.y * 32;

    float acc00 = 0.f, acc01 = 0.f, acc10 = 0.f, acc11 = 0.f;

    for (int kc = 0; kc < 125; kc += 16) {
#pragma unroll
        for (int it = 0; it < 2; ++it) {
            int idx = tid + it * 256;
            int mm = idx >> 4, kk = idx & 15;
            int k = kc + kk;
            int m = m0 + mm;
            int ra = dir ? (T_SEQ - 1 - m) : m;
            As[kk][mm] = (k < 125) ? x[(long)ra * 125 + k] : 0.f;
            int n = n0 + mm;
            Bs[kk][mm] = (n < GATES && k < 125) ? W[(long)n * 125 + k] : 0.f;
        }
        __syncthreads();
#pragma unroll
        for (int kk = 0; kk < 16; ++kk) {
            float2 av = *(const float2*)&As[kk][2 * ti];
            float2 bv = *(const float2*)&Bs[kk][2 * tn];
            acc00 = fmaf(av.x, bv.x, acc00);
            acc01 = fmaf(av.x, bv.y, acc01);
            acc10 = fmaf(av.y, bv.x, acc10);
            acc11 = fmaf(av.y, bv.y, acc11);
        }
        __syncthreads();
    }

    int m_ = m0 + 2 * ti;
    int n_ = n0 + 2 * tn;
    float b0 = 0.f, b1v = 0.f;
    if (n_ < GATES)     b0  = bi[n_] + bh[n_];
    if (n_ + 1 < GATES) b1v = bi[n_ + 1] + bh[n_ + 1];
    if (n_ < GATES) {
        C[(long)m_ * GATES + n_]       = acc00 + b0;
        C[(long)(m_ + 1) * GATES + n_] = acc10 + b0;
    }
    if (n_ + 1 < GATES) {
        C[(long)m_ * GATES + n_ + 1]       = acc01 + b1v;
        C[(long)(m_ + 1) * GATES + n_ + 1] = acc11 + b1v;
    }
}

// ---------------------------------------------------------------------------
// Pa / Pb in one launch. grid (16,16,2), block 256.
// ---------------------------------------------------------------------------
__global__ void __launch_bounds__(256) pab_kernel(
    const float* __restrict__ H,
    const float* __restrict__ W1,
    const float* __restrict__ b1,
    float* __restrict__ P)
{
    const int z = blockIdx.z;
    const float* __restrict__ B = W1 + (z ? DHID : 0);
    float* __restrict__ C = P + (long)z * NN * MLPH;

    __shared__ float As[16][34];
    __shared__ float Bs[16][34];

    const int tid = threadIdx.x;
    const int ti = tid & 15;
    const int tn = tid >> 4;
    const int m0 = blockIdx.x * 32;
    const int n0 = blockIdx.y * 32;

    float acc00 = 0.f, acc01 = 0.f, acc10 = 0.f, acc11 = 0.f;

    for (int kc = 0; kc < DHID; kc += 16) {
#pragma unroll
        for (int it = 0; it < 2; ++it) {
            int idx = tid + it * 256;
            int mm = idx >> 4, kk = idx & 15;
            int k = kc + kk;
            As[kk][mm] = (k < DHID) ? H[(long)(m0 + mm) * DHID + k] : 0.f;
            Bs[kk][mm] = (k < DHID) ? B[(long)(n0 + mm) * 500 + k] : 0.f;
        }
        __syncthreads();
#pragma unroll
        for (int kk = 0; kk < 16; ++kk) {
            float2 av = *(const float2*)&As[kk][2 * ti];
            float2 bv = *(const float2*)&Bs[kk][2 * tn];
            acc00 = fmaf(av.x, bv.x, acc00);
            acc01 = fmaf(av.x, bv.y, acc01);
            acc10 = fmaf(av.y, bv.x, acc10);
            acc11 = fmaf(av.y, bv.y, acc11);
        }
        __syncthreads();
    }

    int m_ = m0 + 2 * ti;
    int n_ = n0 + 2 * tn;
    float b0 = 0.f, b1v = 0.f;
    if (z) { b0 = b1[n_]; b1v = b1[n_ + 1]; }
    C[(long)m_ * MLPH + n_]           = acc00 + b0;
    C[(long)m_ * MLPH + n_ + 1]       = acc01 + b1v;
    C[(long)(m_ + 1) * MLPH + n_]     = acc10 + b0;
    C[(long)(m_ + 1) * MLPH + n_ + 1] = acc11 + b1v;
}

// ---------------------------------------------------------------------------
// LSTM recurrence, intra-warp gate pairing + single barrier + double-buffered h.
// grid = 2 (dir), block = 256 (8 warps).
// Warp w, lane L: unit u = 16w + (L & 15); hi = L >> 4.
//   hi 0 -> rows (u, 250+u)      = (i, g)
//   hi 1 -> rows (125+u, 375+u)  = (f, o)   [rB clamped to 499 for pad units]
// i*g crosses lanes via shfl.xor 16; hi lanes own c and h.
// h double-buffered: step t reads sh_h[t&1], writes sh_h[(t+1)&1].
// Weights: cols 0..79 fp32 in regs (2x40 ull = 160 regs), cols 80..127 bf16
//   in smem (6 x uint4 per row, cols >=125 zero) -> ~50 free regs so ptxas
//   can pipeline the per-step LDS stream (R10 had only ~11 free).
// ---------------------------------------------------------------------------
__global__ void __launch_bounds__(256, 1) lstm_kernel(
    const float* __restrict__ Whh_f,
    const float* __restrict__ Whh_b,
    const float* __restrict__ A,     // [2][512][500]
    float* __restrict__ H)           // [512][250]
{
    __shared__ __align__(16) uint4 sh_wb[6 * 500];   // bf16 weights, 48KB
    __shared__ __align__(16) float sh_h[256];        // double-buffered h

    const int tid = threadIdx.x;
    const int dir = blockIdx.x;
    const float* __restrict__ Whh = dir ? Whh_b : Whh_f;
    const float* __restrict__ Ad = A + dir * (T_SEQ * GATES);

    const int lane = tid & 31;
    const int w    = tid >> 5;
    const int hi   = lane >> 4;                 // 0 = (i,g), 1 = (f,o)
    const int u    = (w << 4) | (lane & 15);    // unit 0..127 (125..127 pad)
    const bool st_ok = (u < HID);
    int rA = hi ? (125 + u) : u;                // <= 252, always in bounds
    int rB = hi ? (375 + u) : (250 + u);
    if (rB > 499) rB = 499;                     // clamp pad units

    // activation constants: vB = m*tanh(m*sB) + a0  (sigmoid for hi, tanh lo)
    const float m_vb  = hi ? 0.5f : 1.0f;
    const float a0_vb = hi ? 0.5f : 0.0f;

    // stage bf16 smem weights: 6 uint4-granules of 8 cols, cols 80..127
    for (int idx = tid; idx < 6 * 500; idx += 256) {
        int q = idx / 500, rr = idx - q * 500;
        const float* wp = Whh + rr * 125;
        unsigned int uu[4];
#pragma unroll
        for (int j = 0; j < 4; ++j) {
            int c0 = 80 + 8 * q + 2 * j, c1 = c0 + 1;
            unsigned short b0 = (c0 < 125) ?
                __bfloat16_as_ushort(__float2bfloat16_rn(wp[c0])) : 0;
            unsigned short b1 = (c1 < 125) ?
                __bfloat16_as_ushort(__float2bfloat16_rn(wp[c1])) : 0;
            uu[j] = ((unsigned int)b1 << 16) | b0;
        }
        sh_wb[q * 500 + rr] = make_uint4(uu[0], uu[1], uu[2], uu[3]);
    }

    // register weights: cols 0..79 of both rows, packed ull
    ull wA[40], wB[40];
    {
        const float* fA = Whh + rA * 125;
        const float* fB = Whh + rB * 125;
#pragma unroll
        for (int p = 0; p < 40; ++p) {
            float2 tA = make_float2(fA[2 * p], fA[2 * p + 1]);
            float2 tB = make_float2(fB[2 * p], fB[2 * p + 1]);
            wA[p] = *(ull*)&tA;
            wB[p] = *(ull*)&tB;
        }
    }

    sh_h[tid] = 0.f;                 // zero both h buffers (incl. pads)
    float creg = 0.f;
    float aA = Ad[rA];
    float aB = Ad[rB];
    __syncthreads();

    for (int t = 0; t < T_SEQ; ++t) {
        const ulonglong2* h2 = (const ulonglong2*)(sh_h + ((t & 1) << 7));
        float* hw = sh_h + (((t + 1) & 1) << 7);
        const bool has_next = (t < T_SEQ - 1);
        float aA_n = has_next ? Ad[(t + 1) * GATES + rA] : 0.f;
        float aB_n = has_next ? Ad[(t + 1) * GATES + rB] : 0.f;

        ull accA0 = 0ull, accA1 = 0ull, accB0 = 0ull, accB1 = 0ull;
        // smem bf16 section first (cols 80..127) so its loads issue early
#pragma unroll
        for (int q = 0; q < 6; ++q) {
            ulonglong2 ha = h2[20 + 2 * q];
            ulonglong2 hb = h2[21 + 2 * q];
            uint4 wa = sh_wb[q * 500 + rA];
            uint4 wb = sh_wb[q * 500 + rB];
            accA0 = ffma2u(unpk(wa.x), ha.x, accA0);
            accA1 = ffma2u(unpk(wa.y), ha.y, accA1);
            accA0 = ffma2u(unpk(wa.z), hb.x, accA0);
            accA1 = ffma2u(unpk(wa.w), hb.y, accA1);
            accB0 = ffma2u(unpk(wb.x), ha.x, accB0);
            accB1 = ffma2u(unpk(wb.y), ha.y, accB1);
            accB0 = ffma2u(unpk(wb.z), hb.x, accB0);
            accB1 = ffma2u(unpk(wb.w), hb.y, accB1);
        }
        // register fp32 section (cols 0..79)
#pragma unroll
        for (int p = 0; p < 20; ++p) {
            ulonglong2 hv = h2[p];
            accA0 = ffma2u(wA[2 * p],     hv.x, accA0);
            accA1 = ffma2u(wA[2 * p + 1], hv.y, accA1);
            accB0 = ffma2u(wB[2 * p],     hv.x, accB0);
            accB1 = ffma2u(wB[2 * p + 1], hv.y, accB1);
        }
        float2 fa = u2f2(fadd2u(accA0, accA1));
        float2 fb = u2f2(fadd2u(accB0, accB1));
        float sA = fa.x + fa.y + aA;
        float sB = fb.x + fb.y + aB;

        float vA = sig_mufu(sA);                            // i (lo) or f (hi)
        float vB = fmaf(m_vb, tanh_mufu(m_vb * sB), a0_vb); // g (lo) or o (hi)
        float ig  = vA * vB;                                // i*g on lo lanes
        float igx = __shfl_xor_sync(0xffffffffu, ig, 16);   // hi gets i*g
        creg = vA * creg + igx;          // hi: f*c + i*g ; lo: bounded garbage
        float hv = vB * tanh_mufu(creg); // hi: o*tanh(c)
        if (hi && st_ok) {
            hw[u] = hv;
            int row = dir ? (T_SEQ - 1 - t) : t;
            H[row * DHID + dir * HID + u] = hv;
        }
        __syncthreads();
        aA = aA_n; aB = aB_n;
    }
}

// ---------------------------------------------------------------------------
// Pairwise MLP contraction:
//   out[j][i] = b2 + sum_k W2[k] * tanh(Pa[i][k] + Pb[j][k])
// ---------------------------------------------------------------------------
__global__ void __launch_bounds__(256) pair_kernel(
    const float* __restrict__ Pa,   // [512][512]
    const float* __restrict__ Pb,   // [512][512] (b1 folded in)
    const float* __restrict__ W2,   // [512]
    const float* __restrict__ b2,   // [1]
    float* __restrict__ out)        // [512][512]  row=j, col=i
{
    __shared__ float pas[64][34];
    __shared__ float pbs[64][34];
    __shared__ float w2s[64];

    const int tid = threadIdx.x;
    const int ti = tid & 15;     // i pair
    const int tj = tid >> 4;     // j pair
    const int i0 = blockIdx.x * 32;
    const int j0 = blockIdx.y * 32;

    float acc00 = 0.f, acc01 = 0.f, acc10 = 0.f, acc11 = 0.f;

    for (int kc = 0; kc < MLPH; kc += 64) {
#pragma unroll
        for (int it = 0; it < 2; ++it) {
            int idx = tid + it * 256;
            int row = idx >> 4, q = idx & 15;
            float4 va = *(const float4*)&Pa[(long)(i0 + row) * MLPH + kc + 4 * q];
            pas[4 * q + 0][row] = va.x; pas[4 * q + 1][row] = va.y;
            pas[4 * q + 2][row] = va.z; pas[4 * q + 3][row] = va.w;
            float4 vb = *(const float4*)&Pb[(long)(j0 + row) * MLPH + kc + 4 * q];
            pbs[4 * q + 0][row] = vb.x; pbs[4 * q + 1][row] = vb.y;
            pbs[4 * q + 2][row] = vb.z; pbs[4 * q + 3][row] = vb.w;
        }
        if (tid < 16) {
            float4 w = *(const float4*)&W2[kc + 4 * tid];
            w2s[4 * tid + 0] = w.x; w2s[4 * tid + 1] = w.y;
            w2s[4 * tid + 2] = w.z; w2s[4 * tid + 3] = w.w;
        }
        __syncthreads();
#pragma unroll
        for (int kk = 0; kk < 64; ++kk) {
            float w = w2s[kk];
            float2 a = *(const float2*)&pas[kk][2 * ti];
            float2 b = *(const float2*)&pbs[kk][2 * tj];
            acc00 = fmaf(w, tanh_mufu(a.x + b.x), acc00);
            acc01 = fmaf(w, tanh_mufu(a.x + b.y), acc01);
            acc10 = fmaf(w, tanh_mufu(a.y + b.x), acc10);
            acc11 = fmaf(w, tanh_mufu(a.y + b.y), acc11);
        }
        __syncthreads();
    }

    float bb = b2[0];
    int i = i0 + 2 * ti;
    int j = j0 + 2 * tj;
    *(float2*)&out[(long)j * NN + i]       = make_float2(acc00 + bb, acc10 + bb);
    *(float2*)&out[(long)(j + 1) * NN + i] = make_float2(acc01 + bb, acc11 + bb);
}

// ---------------------------------------------------------------------------
// launch
// ---------------------------------------------------------------------------
extern "C" void kernel_launch(void* const* d_in, const int* in_sizes, int n_in,
                              void* d_out, int out_size)
{
    const float* x     = (const float*)d_in[0];   // (512,1,125)
    const float* Wih_f = (const float*)d_in[1];
    const float* Whh_f = (const float*)d_in[2];
    const float* bih_f = (const float*)d_in[3];
    const float* bhh_f = (const float*)d_in[4];
    const float* Wih_b = (const float*)d_in[5];
    const float* Whh_b = (const float*)d_in[6];
    const float* bih_b = (const float*)d_in[7];
    const float* bhh_b = (const float*)d_in[8];
    const float* W1    = (const float*)d_in[9];   // (512,500)
    const float* b1    = (const float*)d_in[10];  // (512)
    const float* W2    = (const float*)d_in[11];  // (1,512)
    const float* b2    = (const float*)d_in[12];  // (1)
    float* out = (float*)d_out;

    float *pA, *pH, *pP;
    cudaGetSymbolAddress((void**)&pA, g_A);
    cudaGetSymbolAddress((void**)&pH, g_H);
    cudaGetSymbolAddress((void**)&pP, g_P);
    float* pPa = pP;
    float* pPb = pP + NN * MLPH;

    dim3 blk(256);
    // keep launch-slot layout so ncu's captured launch stays on lstm_kernel
    nudge_kernel<<<1, 32>>>();
    nudge_kernel<<<1, 32>>>();
    proj_kernel<<<dim3(16, 16, 2), blk>>>(x, Wih_f, bih_f, bhh_f,
                                          Wih_b, bih_b, bhh_b, pA);
    lstm_kernel<<<2, 256>>>(Whh_f, Whh_b, pA, pH);
    pab_kernel<<<dim3(16, 16, 2), blk>>>(pH, W1, b1, pP);
    pair_kernel<<<dim3(16, 16), blk>>>(pPa, pPb, W2, b2, out);
}

// round 13
// speedup vs baseline: 1.6926x; 1.6926x over previous
#include <cuda_runtime.h>
#include <cuda_bf16.h>
#include <math.h>
#include <stdint.h>

#define T_SEQ   512
#define GATES   500
#define HID     125
#define DHID    250      // 2*HID
#define MLPH    512
#define NN      512

// Scratch (device globals; no allocation allowed)
__device__ float g_A[2 * T_SEQ * GATES];   // input projections (fwd/bwd)
__device__ float g_H[T_SEQ * DHID];        // concat hidden states
__device__ float g_P[2 * NN * MLPH];       // Pa, Pb(+b1)

// ---------------------------------------------------------------------------
// helpers
// ---------------------------------------------------------------------------
typedef unsigned long long ull;

__device__ __forceinline__ ull ffma2u(ull a, ull b, ull c) {
    ull d;
    asm("fma.rn.f32x2 %0, %1, %2, %3;" : "=l"(d) : "l"(a), "l"(b), "l"(c));
    return d;
}
__device__ __forceinline__ ull fadd2u(ull a, ull b) {
    ull d;
    asm("add.rn.f32x2 %0, %1, %2;" : "=l"(d) : "l"(a), "l"(b));
    return d;
}
__device__ __forceinline__ float2 u2f2(ull v) {
    float2 r;
    asm("mov.b64 {%0, %1}, %2;" : "=f"(r.x), "=f"(r.y) : "l"(v));
    return r;
}
__device__ __forceinline__ float tanh_mufu(float x) {
    float y;
    asm("tanh.approx.f32 %0, %1;" : "=f"(y) : "f"(x));
    return y;
}
__device__ __forceinline__ unsigned int smem_u32(const void* p) {
    unsigned int a;
    asm("{ .reg .u64 t; cvta.to.shared.u64 t, %1; cvt.u32.u64 %0, t; }"
        : "=r"(a) : "l"(p));
    return a;
}
__device__ __forceinline__ unsigned int mapa_u32(unsigned int addr, unsigned int rank) {
    unsigned int r;
    asm("mapa.shared::cluster.u32 %0, %1, %2;" : "=r"(r) : "r"(addr), "r"(rank));
    return r;
}
__device__ __forceinline__ void st_async_b32(unsigned int raddr, float v, unsigned int rmbar) {
    asm volatile(
        "st.async.shared::cluster.mbarrier::complete_tx::bytes.b32 [%0], %1, [%2];"
        :: "r"(raddr), "r"(__float_as_uint(v)), "r"(rmbar) : "memory");
}
__device__ __forceinline__ void mbar_init(unsigned int mbar, unsigned int cnt) {
    asm volatile("mbarrier.init.shared.b64 [%0], %1;" :: "r"(mbar), "r"(cnt) : "memory");
}
__device__ __forceinline__ void mbar_arrive_expect_tx(unsigned int mbar, unsigned int tx) {
    asm volatile("mbarrier.arrive.expect_tx.shared.b64 _, [%0], %1;"
                 :: "r"(mbar), "r"(tx) : "memory");
}
__device__ __forceinline__ void mbar_wait_parity(unsigned int mbar, unsigned int parity) {
    asm volatile(
        "{\n\t.reg .pred P;\n\t"
        "WL_%=:\n\t"
        "mbarrier.try_wait.parity.acquire.cluster.shared::cta.b64 P, [%0], %1, 0x989680;\n\t"
        "@P bra.uni WD_%=;\n\t"
        "bra.uni WL_%=;\n\t"
        "WD_%=:\n\t}"
        :: "r"(mbar), "r"(parity) : "memory");
}
__device__ __forceinline__ void cluster_sync() {
    asm volatile("barrier.cluster.arrive.aligned;" ::: "memory");
    asm volatile("barrier.cluster.wait.aligned;" ::: "memory");
}

// no-op kernels to keep the ncu capture slot on lstm_kernel
__device__ int g_sink;
__global__ void nudge_kernel() {
    if (threadIdx.x > 4096) g_sink = 1;   // never taken
}

// ---------------------------------------------------------------------------
// Input projection, both directions in one launch.
// ---------------------------------------------------------------------------
__global__ void __launch_bounds__(256) proj_kernel(
    const float* __restrict__ x,
    const float* __restrict__ Wih_f, const float* __restrict__ bih_f,
    const float* __restrict__ bhh_f,
    const float* __restrict__ Wih_b, const float* __restrict__ bih_b,
    const float* __restrict__ bhh_b,
    float* __restrict__ Aout)
{
    const int dir = blockIdx.z;
    const float* __restrict__ W  = dir ? Wih_b : Wih_f;
    const float* __restrict__ bi = dir ? bih_b : bih_f;
    const float* __restrict__ bh = dir ? bhh_b : bhh_f;
    float* __restrict__ C = Aout + dir * (T_SEQ * GATES);

    __shared__ float As[16][34];
    __shared__ float Bs[16][34];

    const int tid = threadIdx.x;
    const int ti = tid & 15;
    const int tn = tid >> 4;
    const int m0 = blockIdx.x * 32;
    const int n0 = blockIdx.y * 32;

    float acc00 = 0.f, acc01 = 0.f, acc10 = 0.f, acc11 = 0.f;

    for (int kc = 0; kc < 125; kc += 16) {
#pragma unroll
        for (int it = 0; it < 2; ++it) {
            int idx = tid + it * 256;
            int mm = idx >> 4, kk = idx & 15;
            int k = kc + kk;
            int m = m0 + mm;
            int ra = dir ? (T_SEQ - 1 - m) : m;
            As[kk][mm] = (k < 125) ? x[(long)ra * 125 + k] : 0.f;
            int n = n0 + mm;
            Bs[kk][mm] = (n < GATES && k < 125) ? W[(long)n * 125 + k] : 0.f;
        }
        __syncthreads();
#pragma unroll
        for (int kk = 0; kk < 16; ++kk) {
            float2 av = *(const float2*)&As[kk][2 * ti];
            float2 bv = *(const float2*)&Bs[kk][2 * tn];
            acc00 = fmaf(av.x, bv.x, acc00);
            acc01 = fmaf(av.x, bv.y, acc01);
            acc10 = fmaf(av.y, bv.x, acc10);
            acc11 = fmaf(av.y, bv.y, acc11);
        }
        __syncthreads();
    }

    int m_ = m0 + 2 * ti;
    int n_ = n0 + 2 * tn;
    float b0 = 0.f, b1v = 0.f;
    if (n_ < GATES)     b0  = bi[n_] + bh[n_];
    if (n_ + 1 < GATES) b1v = bi[n_ + 1] + bh[n_ + 1];
    if (n_ < GATES) {
        C[(long)m_ * GATES + n_]       = acc00 + b0;
        C[(long)(m_ + 1) * GATES + n_] = acc10 + b0;
    }
    if (n_ + 1 < GATES) {
        C[(long)m_ * GATES + n_ + 1]       = acc01 + b1v;
        C[(long)(m_ + 1) * GATES + n_ + 1] = acc11 + b1v;
    }
}

// ---------------------------------------------------------------------------
// Pa / Pb in one launch. grid (16,16,2), block 256.
// ---------------------------------------------------------------------------
__global__ void __launch_bounds__(256) pab_kernel(
    const float* __restrict__ H,
    const float* __restrict__ W1,
    const float* __restrict__ b1,
    float* __restrict__ P)
{
    const int z = blockIdx.z;
    const float* __restrict__ B = W1 + (z ? DHID : 0);
    float* __restrict__ C = P + (long)z * NN * MLPH;

    __shared__ float As[16][34];
    __shared__ float Bs[16][34];

    const int tid = threadIdx.x;
    const int ti = tid & 15;
    const int tn = tid >> 4;
    const int m0 = blockIdx.x * 32;
    const int n0 = blockIdx.y * 32;

    float acc00 = 0.f, acc01 = 0.f, acc10 = 0.f, acc11 = 0.f;

    for (int kc = 0; kc < DHID; kc += 16) {
#pragma unroll
        for (int it = 0; it < 2; ++it) {
            int idx = tid + it * 256;
            int mm = idx >> 4, kk = idx & 15;
            int k = kc + kk;
            As[kk][mm] = (k < DHID) ? H[(long)(m0 + mm) * DHID + k] : 0.f;
            Bs[kk][mm] = (k < DHID) ? B[(long)(n0 + mm) * 500 + k] : 0.f;
        }
        __syncthreads();
#pragma unroll
        for (int kk = 0; kk < 16; ++kk) {
            float2 av = *(const float2*)&As[kk][2 * ti];
            float2 bv = *(const float2*)&Bs[kk][2 * tn];
            acc00 = fmaf(av.x, bv.x, acc00);
            acc01 = fmaf(av.x, bv.y, acc01);
            acc10 = fmaf(av.y, bv.x, acc10);
            acc11 = fmaf(av.y, bv.y, acc11);
        }
        __syncthreads();
    }

    int m_ = m0 + 2 * ti;
    int n_ = n0 + 2 * tn;
    float b0 = 0.f, b1v = 0.f;
    if (z) { b0 = b1[n_]; b1v = b1[n_ + 1]; }
    C[(long)m_ * MLPH + n_]           = acc00 + b0;
    C[(long)m_ * MLPH + n_ + 1]       = acc01 + b1v;
    C[(long)(m_ + 1) * MLPH + n_]     = acc10 + b0;
    C[(long)(m_ + 1) * MLPH + n_ + 1] = acc11 + b1v;
}

// ---------------------------------------------------------------------------
// LSTM recurrence, 4-CTA cluster per direction, split by gate.
// grid = 8, cluster = 4. dir = blockIdx.x >> 2; gate g = cluster rank.
// Block 256: warp w, lane L: u = 16w + (L&15); hi = L>>4 (column half).
// Thread computes gate row r = g*125 + u (clamped), cols [64*hi, 64*hi+64),
// all weights fp32 in registers (32 ull). Halves combined via shfl.xor 16.
// Activated gate values broadcast to all 4 CTAs via st.async + mbarrier
// (double-buffered gbuf, arm-ahead expect_tx); every CTA redundantly
// computes c and h. FMA floor per SM: 128x128/64 = 256 cyc/step.
// ---------------------------------------------------------------------------
#define TXB (4u * 128u * 4u)   // bytes per target mbarrier per step

__global__ void __cluster_dims__(4, 1, 1) __launch_bounds__(256, 1) lstm_kernel(
    const float* __restrict__ Whh_f,
    const float* __restrict__ Whh_b,
    const float* __restrict__ A,     // [2][512][500]
    float* __restrict__ H)           // [512][250]
{
    __shared__ __align__(16) float sh_h[2][128];    // double-buffered h
    __shared__ __align__(16) float gbuf[2][4][128]; // [phase][gate][unit]
    __shared__ __align__(8)  ull   mbar[2];

    const int tid = threadIdx.x;
    const int g   = blockIdx.x & 3;          // cluster rank = gate (i,f,g,o)
    const int dir = blockIdx.x >> 2;
    const float* __restrict__ Whh = dir ? Whh_b : Whh_f;
    const float* __restrict__ Ad = A + dir * (T_SEQ * GATES);

    const int lane = tid & 31;
    const int w    = tid >> 5;
    const int hi   = lane >> 4;               // column half 0/1
    const int u    = (w << 4) | (lane & 15);  // unit 0..127 (125..127 pad)
    const bool st_ok = (u < HID);
    int r = g * 125 + u;
    if (r > 499) r = 499;                     // clamp pad rows (bounded values)

    // activation: g-gate (rank 2) -> tanh ; others -> sigmoid
    const float m_act  = (g == 2) ? 1.0f : 0.5f;
    const float a0_act = (g == 2) ? 0.0f : 0.5f;

    // register weights: 32 packed pairs = cols 64*hi .. 64*hi+63 (>=125 -> 0)
    ull wreg[32];
    {
        const float* wf = Whh + r * 125;
#pragma unroll
        for (int p = 0; p < 32; ++p) {
            int c0 = 64 * hi + 2 * p;
            float v0 = (c0 < 125)     ? wf[c0]     : 0.f;
            float v1 = (c0 + 1 < 125) ? wf[c0 + 1] : 0.f;
            float2 t = make_float2(v0, v1);
            wreg[p] = *(ull*)&t;
        }
    }

    // init smem / barriers
    ((float*)sh_h)[tid] = 0.f;                // zero both h buffers
    const unsigned int mb0 = smem_u32(&mbar[0]);
    const unsigned int mb1 = smem_u32(&mbar[1]);
    if (tid == 0) {
        mbar_init(mb0, 1);
        mbar_init(mb1, 1);
        mbar_arrive_expect_tx(mb0, TXB);      // arm step 0
        mbar_arrive_expect_tx(mb1, TXB);      // arm step 1
    }
    float creg = 0.f;
    float a_cur = Ad[r];
    __syncthreads();
    cluster_sync();                            // barriers visible cluster-wide

    // precomputed remote addresses: hi half stores to ranks {2hi, 2hi+1}
    const unsigned int rk0 = 2 * hi, rk1 = 2 * hi + 1;
    const unsigned int la0 = smem_u32(&gbuf[0][g][u]);
    const unsigned int la1 = smem_u32(&gbuf[1][g][u]);
    const unsigned int d00 = mapa_u32(la0, rk0), d01 = mapa_u32(la0, rk1);
    const unsigned int d10 = mapa_u32(la1, rk0), d11 = mapa_u32(la1, rk1);
    const unsigned int m00 = mapa_u32(mb0, rk0),  m01 = mapa_u32(mb0, rk1);
    const unsigned int m10 = mapa_u32(mb1, rk0),  m11 = mapa_u32(mb1, rk1);

    for (int t = 0; t < T_SEQ; ++t) {
        const int b = t & 1;
        const bool has_next = (t < T_SEQ - 1);
        float a_next = has_next ? Ad[(t + 1) * GATES + r] : 0.f;

        // matvec: 16 h-granules (cols 64*hi ..), weights in registers
        const ulonglong2* h2 = (const ulonglong2*)sh_h[b];
        ull acc0 = 0ull, acc1 = 0ull;
#pragma unroll
        for (int p = 0; p < 16; ++p) {
            ulonglong2 hv = h2[16 * hi + p];
            acc0 = ffma2u(wreg[2 * p],     hv.x, acc0);
            acc1 = ffma2u(wreg[2 * p + 1], hv.y, acc1);
        }
        float2 fs = u2f2(fadd2u(acc0, acc1));
        float part = fs.x + fs.y;
        float s = part + __shfl_xor_sync(0xffffffffu, part, 16) + a_cur;
        float act = fmaf(m_act, tanh_mufu(m_act * s), a0_act);

        // broadcast activated gate value to my two target ranks
        if (b == 0) {
            st_async_b32(d00, act, m00);
            st_async_b32(d01, act, m01);
        } else {
            st_async_b32(d10, act, m10);
            st_async_b32(d11, act, m11);
        }

        // wait for all 4 gates from all CTAs
        mbar_wait_parity(b ? mb1 : mb0, (t >> 1) & 1);
        if (tid == 0)
            mbar_arrive_expect_tx(b ? mb1 : mb0, TXB);   // arm step t+2

        // combine (redundant on every CTA)
        float iv = gbuf[b][0][u];
        float fv = gbuf[b][1][u];
        float gv = gbuf[b][2][u];
        float ov = gbuf[b][3][u];
        creg = fv * creg + iv * gv;
        float hv = ov * tanh_mufu(creg);
        if (hi == 0 && st_ok) {
            sh_h[b ^ 1][u] = hv;
            if (g == 0) {
                int row = dir ? (T_SEQ - 1 - t) : t;
                H[row * DHID + dir * HID + u] = hv;
            }
        }
        __syncthreads();
        a_cur = a_next;
    }
    cluster_sync();
}

// ---------------------------------------------------------------------------
// Pairwise MLP contraction:
//   out[j][i] = b2 + sum_k W2[k] * tanh(Pa[i][k] + Pb[j][k])
// ---------------------------------------------------------------------------
__global__ void __launch_bounds__(256) pair_kernel(
    const float* __restrict__ Pa,   // [512][512]
    const float* __restrict__ Pb,   // [512][512] (b1 folded in)
    const float* __restrict__ W2,   // [512]
    const float* __restrict__ b2,   // [1]
    float* __restrict__ out)        // [512][512]  row=j, col=i
{
    __shared__ float pas[64][34];
    __shared__ float pbs[64][34];
    __shared__ float w2s[64];

    const int tid = threadIdx.x;
    const int ti = tid & 15;     // i pair
    const int tj = tid >> 4;     // j pair
    const int i0 = blockIdx.x * 32;
    const int j0 = blockIdx.y * 32;

    float acc00 = 0.f, acc01 = 0.f, acc10 = 0.f, acc11 = 0.f;

    for (int kc = 0; kc < MLPH; kc += 64) {
#pragma unroll
        for (int it = 0; it < 2; ++it) {
            int idx = tid + it * 256;
            int row = idx >> 4, q = idx & 15;
            float4 va = *(const float4*)&Pa[(long)(i0 + row) * MLPH + kc + 4 * q];
            pas[4 * q + 0][row] = va.x; pas[4 * q + 1][row] = va.y;
            pas[4 * q + 2][row] = va.z; pas[4 * q + 3][row] = va.w;
            float4 vb = *(const float4*)&Pb[(long)(j0 + row) * MLPH + kc + 4 * q];
            pbs[4 * q + 0][row] = vb.x; pbs[4 * q + 1][row] = vb.y;
            pbs[4 * q + 2][row] = vb.z; pbs[4 * q + 3][row] = vb.w;
        }
        if (tid < 16) {
            float4 w = *(const float4*)&W2[kc + 4 * tid];
            w2s[4 * tid + 0] = w.x; w2s[4 * tid + 1] = w.y;
            w2s[4 * tid + 2] = w.z; w2s[4 * tid + 3] = w.w;
        }
        __syncthreads();
#pragma unroll
        for (int kk = 0; kk < 64; ++kk) {
            float w = w2s[kk];
            float2 a = *(const float2*)&pas[kk][2 * ti];
            float2 b = *(const float2*)&pbs[kk][2 * tj];
            acc00 = fmaf(w, tanh_mufu(a.x + b.x), acc00);
            acc01 = fmaf(w, tanh_mufu(a.x + b.y), acc01);
            acc10 = fmaf(w, tanh_mufu(a.y + b.x), acc10);
            acc11 = fmaf(w, tanh_mufu(a.y + b.y), acc11);
        }
        __syncthreads();
    }

    float bb = b2[0];
    int i = i0 + 2 * ti;
    int j = j0 + 2 * tj;
    *(float2*)&out[(long)j * NN + i]       = make_float2(acc00 + bb, acc10 + bb);
    *(float2*)&out[(long)(j + 1) * NN + i] = make_float2(acc01 + bb, acc11 + bb);
}

// ---------------------------------------------------------------------------
// launch
// ---------------------------------------------------------------------------
extern "C" void kernel_launch(void* const* d_in, const int* in_sizes, int n_in,
                              void* d_out, int out_size)
{
    const float* x     = (const float*)d_in[0];   // (512,1,125)
    const float* Wih_f = (const float*)d_in[1];
    const float* Whh_f = (const float*)d_in[2];
    const float* bih_f = (const float*)d_in[3];
    const float* bhh_f = (const float*)d_in[4];
    const float* Wih_b = (const float*)d_in[5];
    const float* Whh_b = (const float*)d_in[6];
    const float* bih_b = (const float*)d_in[7];
    const float* bhh_b = (const float*)d_in[8];
    const float* W1    = (const float*)d_in[9];   // (512,500)
    const float* b1    = (const float*)d_in[10];  // (512)
    const float* W2    = (const float*)d_in[11];  // (1,512)
    const float* b2    = (const float*)d_in[12];  // (1)
    float* out = (float*)d_out;

    float *pA, *pH, *pP;
    cudaGetSymbolAddress((void**)&pA, g_A);
    cudaGetSymbolAddress((void**)&pH, g_H);
    cudaGetSymbolAddress((void**)&pP, g_P);
    float* pPa = pP;
    float* pPb = pP + NN * MLPH;

    dim3 blk(256);
    // keep launch-slot layout so ncu's captured launch stays on lstm_kernel
    nudge_kernel<<<1, 32>>>();
    nudge_kernel<<<1, 32>>>();
    proj_kernel<<<dim3(16, 16, 2), blk>>>(x, Wih_f, bih_f, bhh_f,
                                          Wih_b, bih_b, bhh_b, pA);
    lstm_kernel<<<8, 256>>>(Whh_f, Whh_b, pA, pH);
    pab_kernel<<<dim3(16, 16, 2), blk>>>(pH, W1, b1, pP);
    pair_kernel<<<dim3(16, 16), blk>>>(pPa, pPb, W2, b2, out);
}